// round 2
// baseline (speedup 1.0000x reference)
#include <cuda_runtime.h>

// ---------------------------------------------------------------------------
// SelfAttention: out = softmax((x Wq + bq)(kv Wk + bk)^T) (kv Wv + bv) Wo + bo
// B=4, Sq=Skv=2048, D=1024, fp32. Two-pass (materialized scores) formulation:
// every heavy op is a GEMM handled by one tiled SGEMM template.
// ---------------------------------------------------------------------------

#define BATCH 4
#define SEQ   2048
#define DIM   1024

#define BM 128
#define BN 128
#define BK 16
#define TM 8
#define TN 8
#define NTHREADS 256  // (BM/TM)*(BN/TN)

// Scratch (allocation-free rule: __device__ globals)
__device__ float g_Q[(size_t)BATCH * SEQ * DIM];       // 32 MB
__device__ float g_K[(size_t)BATCH * SEQ * DIM];       // 32 MB
__device__ float g_V[(size_t)BATCH * SEQ * DIM];       // 32 MB
__device__ float g_S[(size_t)BATCH * SEQ * SEQ];       // 64 MB (scores / probs)
__device__ float g_C[(size_t)BATCH * SEQ * DIM];       // 32 MB (context)

// ---------------------------------------------------------------------------
// Generic batched SGEMM: C = A * op(B) (+ bias broadcast over rows)
//   A: [M,K] row-major
//   TRANSB=false: B is [K,N] row-major ; TRANSB=true: B is [N,K] row-major
//   blockIdx.z = batch, with element strides sA/sB/sC.
// Requires M%128==0, N%128==0, K%16==0 (true for all shapes here).
// ---------------------------------------------------------------------------
template <bool TRANSB, bool BIAS>
__global__ __launch_bounds__(NTHREADS)
void sgemm_kernel(const float* __restrict__ Ag, const float* __restrict__ Bg,
                  const float* __restrict__ bias, float* __restrict__ Cg,
                  int M, int N, int K,
                  long long sA, long long sB, long long sC)
{
    const float* A = Ag + (long long)blockIdx.z * sA;
    const float* B = Bg + (long long)blockIdx.z * sB;
    float*       C = Cg + (long long)blockIdx.z * sC;

    __shared__ float As[BK][BM];
    __shared__ float Bs[BK][BN];

    const int tid  = threadIdx.x;
    const int bm   = blockIdx.y * BM;
    const int bn   = blockIdx.x * BN;
    const int tcol = (tid & 15) * TN;   // 0..120
    const int trow = (tid >> 4) * TM;   // 0..120

    float acc[TM][TN];
    #pragma unroll
    for (int i = 0; i < TM; ++i)
        #pragma unroll
        for (int j = 0; j < TN; ++j) acc[i][j] = 0.f;

    for (int k0 = 0; k0 < K; k0 += BK) {
        // ---- stage A tile [BM x BK], stored transposed As[k][m] ----
        #pragma unroll
        for (int it = 0; it < 2; ++it) {
            int id  = tid + it * NTHREADS;     // 0..511
            int row = id >> 2;                 // BK/4 = 4 float4 per row
            int kf  = id & 3;
            float4 v = *reinterpret_cast<const float4*>(
                &A[(long long)(bm + row) * K + k0 + kf * 4]);
            As[kf * 4 + 0][row] = v.x;
            As[kf * 4 + 1][row] = v.y;
            As[kf * 4 + 2][row] = v.z;
            As[kf * 4 + 3][row] = v.w;
        }
        // ---- stage B tile -> Bs[k][n] ----
        if (TRANSB) {
            #pragma unroll
            for (int it = 0; it < 2; ++it) {
                int id  = tid + it * NTHREADS;
                int row = id >> 2;             // row within [bn, bn+BN)
                int kf  = id & 3;
                float4 v = *reinterpret_cast<const float4*>(
                    &B[(long long)(bn + row) * K + k0 + kf * 4]);
                Bs[kf * 4 + 0][row] = v.x;
                Bs[kf * 4 + 1][row] = v.y;
                Bs[kf * 4 + 2][row] = v.z;
                Bs[kf * 4 + 3][row] = v.w;
            }
        } else {
            #pragma unroll
            for (int it = 0; it < 2; ++it) {
                int id   = tid + it * NTHREADS;
                int krow = id >> 5;            // BN/4 = 32 float4 per row
                int nf   = id & 31;
                float4 v = *reinterpret_cast<const float4*>(
                    &B[(long long)(k0 + krow) * N + bn + nf * 4]);
                *reinterpret_cast<float4*>(&Bs[krow][nf * 4]) = v;
            }
        }
        __syncthreads();

        // ---- compute ----
        #pragma unroll
        for (int k = 0; k < BK; ++k) {
            float a[TM], b[TN];
            #pragma unroll
            for (int i = 0; i < TM; i += 4)
                *reinterpret_cast<float4*>(&a[i]) =
                    *reinterpret_cast<const float4*>(&As[k][trow + i]);
            #pragma unroll
            for (int j = 0; j < TN; j += 4)
                *reinterpret_cast<float4*>(&b[j]) =
                    *reinterpret_cast<const float4*>(&Bs[k][tcol + j]);
            #pragma unroll
            for (int i = 0; i < TM; ++i)
                #pragma unroll
                for (int j = 0; j < TN; ++j)
                    acc[i][j] = fmaf(a[i], b[j], acc[i][j]);
        }
        __syncthreads();
    }

    // ---- epilogue ----
    float bvals[TN];
    if (BIAS) {
        #pragma unroll
        for (int j = 0; j < TN; ++j) bvals[j] = bias[bn + tcol + j];
    }
    #pragma unroll
    for (int i = 0; i < TM; ++i) {
        float* crow = C + (long long)(bm + trow + i) * N + bn + tcol;
        #pragma unroll
        for (int j0 = 0; j0 < TN; j0 += 4) {
            float4 o;
            o.x = acc[i][j0 + 0] + (BIAS ? bvals[j0 + 0] : 0.f);
            o.y = acc[i][j0 + 1] + (BIAS ? bvals[j0 + 1] : 0.f);
            o.z = acc[i][j0 + 2] + (BIAS ? bvals[j0 + 2] : 0.f);
            o.w = acc[i][j0 + 3] + (BIAS ? bvals[j0 + 3] : 0.f);
            *reinterpret_cast<float4*>(crow + j0) = o;
        }
    }
}

// ---------------------------------------------------------------------------
// Row softmax over SEQ=2048 columns. One 256-thread block per row.
// ---------------------------------------------------------------------------
__global__ __launch_bounds__(256)
void softmax_kernel(float* __restrict__ Sm)
{
    const int n = SEQ;
    float* row = Sm + (size_t)blockIdx.x * n;
    const int tid = threadIdx.x;

    float v[8];
    float m = -3.4e38f;
    #pragma unroll
    for (int i = 0; i < 8; ++i) {
        v[i] = row[tid + 256 * i];
        m = fmaxf(m, v[i]);
    }

    __shared__ float red[8];
    #pragma unroll
    for (int o = 16; o > 0; o >>= 1) m = fmaxf(m, __shfl_xor_sync(0xffffffffu, m, o));
    if ((tid & 31) == 0) red[tid >> 5] = m;
    __syncthreads();
    float bm = red[0];
    #pragma unroll
    for (int w = 1; w < 8; ++w) bm = fmaxf(bm, red[w]);
    __syncthreads();

    float s = 0.f;
    #pragma unroll
    for (int i = 0; i < 8; ++i) {
        v[i] = __expf(v[i] - bm);
        s += v[i];
    }
    #pragma unroll
    for (int o = 16; o > 0; o >>= 1) s += __shfl_xor_sync(0xffffffffu, s, o);
    if ((tid & 31) == 0) red[tid >> 5] = s;
    __syncthreads();
    float bs = 0.f;
    #pragma unroll
    for (int w = 0; w < 8; ++w) bs += red[w];

    const float inv = 1.0f / bs;
    #pragma unroll
    for (int i = 0; i < 8; ++i) row[tid + 256 * i] = v[i] * inv;
}

// ---------------------------------------------------------------------------
// Launch
// ---------------------------------------------------------------------------
extern "C" void kernel_launch(void* const* d_in, const int* in_sizes, int n_in,
                              void* d_out, int out_size)
{
    const float* query = (const float*)d_in[0];
    const float* kv    = (const float*)d_in[1];
    const float* Wq    = (const float*)d_in[2];
    const float* bq    = (const float*)d_in[3];
    const float* Wk    = (const float*)d_in[4];
    const float* bk    = (const float*)d_in[5];
    const float* Wv    = (const float*)d_in[6];
    const float* bv    = (const float*)d_in[7];
    const float* Wo    = (const float*)d_in[8];
    const float* bo    = (const float*)d_in[9];
    float* out = (float*)d_out;

    float *Q, *K, *V, *S, *C;
    cudaGetSymbolAddress((void**)&Q, g_Q);
    cudaGetSymbolAddress((void**)&K, g_K);
    cudaGetSymbolAddress((void**)&V, g_V);
    cudaGetSymbolAddress((void**)&S, g_S);
    cudaGetSymbolAddress((void**)&C, g_C);

    const int M  = BATCH * SEQ;             // 8192
    const long long sQKV = (long long)SEQ * DIM;   // per-batch Q/K/V stride
    const long long sS   = (long long)SEQ * SEQ;   // per-batch score stride

    // Projections: [8192,1024] x [1024,1024] + bias
    {
        dim3 grid(DIM / BN, M / BM, 1);
        sgemm_kernel<false, true><<<grid, NTHREADS>>>(query, Wq, bq, Q, M, DIM, DIM, 0, 0, 0);
        sgemm_kernel<false, true><<<grid, NTHREADS>>>(kv,    Wk, bk, K, M, DIM, DIM, 0, 0, 0);
        sgemm_kernel<false, true><<<grid, NTHREADS>>>(kv,    Wv, bv, V, M, DIM, DIM, 0, 0, 0);
    }

    // Scores: per batch, [2048,1024] x [2048,1024]^T -> [2048,2048]
    {
        dim3 grid(SEQ / BN, SEQ / BM, BATCH);
        sgemm_kernel<true, false><<<grid, NTHREADS>>>(Q, K, nullptr, S,
                                                      SEQ, SEQ, DIM, sQKV, sQKV, sS);
    }

    // Softmax over rows
    softmax_kernel<<<BATCH * SEQ, 256>>>(S);

    // Context: per batch, [2048,2048] x [2048,1024] -> [2048,1024]
    {
        dim3 grid(DIM / BN, SEQ / BM, BATCH);
        sgemm_kernel<false, false><<<grid, NTHREADS>>>(S, V, nullptr, C,
                                                       SEQ, DIM, SEQ, sS, sQKV, sQKV);
    }

    // Output projection: [8192,1024] x [1024,1024] + bias -> d_out
    {
        dim3 grid(DIM / BN, M / BM, 1);
        sgemm_kernel<false, true><<<grid, NTHREADS>>>(C, Wo, bo, out, M, DIM, DIM, 0, 0, 0);
    }
}

// round 7
// speedup vs baseline: 1.0008x; 1.0008x over previous
#include <cuda_runtime.h>

// ---------------------------------------------------------------------------
// SelfAttention: out = softmax((x Wq + bq)(kv Wk + bk)^T) (kv Wv + bv) Wo + bo
// B=4, Sq=Skv=2048, D=1024, fp32. Two-pass (materialized scores) formulation:
// every heavy op is a GEMM handled by one tiled SGEMM template.
// ---------------------------------------------------------------------------

#define BATCH 4
#define SEQ   2048
#define DIM   1024

#define BM 128
#define BN 128
#define BK 16
#define TM 8
#define TN 8
#define NTHREADS 256  // (BM/TM)*(BN/TN)

// Scratch (allocation-free rule: __device__ globals)
__device__ float g_Q[(size_t)BATCH * SEQ * DIM];       // 32 MB
__device__ float g_K[(size_t)BATCH * SEQ * DIM];       // 32 MB
__device__ float g_V[(size_t)BATCH * SEQ * DIM];       // 32 MB
__device__ float g_S[(size_t)BATCH * SEQ * SEQ];       // 64 MB (scores / probs)
__device__ float g_C[(size_t)BATCH * SEQ * DIM];       // 32 MB (context)

// ---------------------------------------------------------------------------
// Generic batched SGEMM: C = A * op(B) (+ bias broadcast over rows)
//   A: [M,K] row-major
//   TRANSB=false: B is [K,N] row-major ; TRANSB=true: B is [N,K] row-major
//   blockIdx.z = batch, with element strides sA/sB/sC.
// Requires M%128==0, N%128==0, K%16==0 (true for all shapes here).
// ---------------------------------------------------------------------------
template <bool TRANSB, bool BIAS>
__global__ __launch_bounds__(NTHREADS)
void sgemm_kernel(const float* __restrict__ Ag, const float* __restrict__ Bg,
                  const float* __restrict__ bias, float* __restrict__ Cg,
                  int M, int N, int K,
                  long long sA, long long sB, long long sC)
{
    const float* A = Ag + (long long)blockIdx.z * sA;
    const float* B = Bg + (long long)blockIdx.z * sB;
    float*       C = Cg + (long long)blockIdx.z * sC;

    __shared__ float As[BK][BM];
    __shared__ float Bs[BK][BN];

    const int tid  = threadIdx.x;
    const int bm   = blockIdx.y * BM;
    const int bn   = blockIdx.x * BN;
    const int tcol = (tid & 15) * TN;   // 0..120
    const int trow = (tid >> 4) * TM;   // 0..120

    float acc[TM][TN];
    #pragma unroll
    for (int i = 0; i < TM; ++i)
        #pragma unroll
        for (int j = 0; j < TN; ++j) acc[i][j] = 0.f;

    for (int k0 = 0; k0 < K; k0 += BK) {
        // ---- stage A tile [BM x BK], stored transposed As[k][m] ----
        #pragma unroll
        for (int it = 0; it < 2; ++it) {
            int id  = tid + it * NTHREADS;     // 0..511
            int row = id >> 2;                 // BK/4 = 4 float4 per row
            int kf  = id & 3;
            float4 v = *reinterpret_cast<const float4*>(
                &A[(long long)(bm + row) * K + k0 + kf * 4]);
            As[kf * 4 + 0][row] = v.x;
            As[kf * 4 + 1][row] = v.y;
            As[kf * 4 + 2][row] = v.z;
            As[kf * 4 + 3][row] = v.w;
        }
        // ---- stage B tile -> Bs[k][n] ----
        if (TRANSB) {
            #pragma unroll
            for (int it = 0; it < 2; ++it) {
                int id  = tid + it * NTHREADS;
                int row = id >> 2;             // row within [bn, bn+BN)
                int kf  = id & 3;
                float4 v = *reinterpret_cast<const float4*>(
                    &B[(long long)(bn + row) * K + k0 + kf * 4]);
                Bs[kf * 4 + 0][row] = v.x;
                Bs[kf * 4 + 1][row] = v.y;
                Bs[kf * 4 + 2][row] = v.z;
                Bs[kf * 4 + 3][row] = v.w;
            }
        } else {
            #pragma unroll
            for (int it = 0; it < 2; ++it) {
                int id   = tid + it * NTHREADS;
                int krow = id >> 5;            // BN/4 = 32 float4 per row
                int nf   = id & 31;
                float4 v = *reinterpret_cast<const float4*>(
                    &B[(long long)(k0 + krow) * N + bn + nf * 4]);
                *reinterpret_cast<float4*>(&Bs[krow][nf * 4]) = v;
            }
        }
        __syncthreads();

        // ---- compute ----
        #pragma unroll
        for (int k = 0; k < BK; ++k) {
            float a[TM], b[TN];
            #pragma unroll
            for (int i = 0; i < TM; i += 4)
                *reinterpret_cast<float4*>(&a[i]) =
                    *reinterpret_cast<const float4*>(&As[k][trow + i]);
            #pragma unroll
            for (int j = 0; j < TN; j += 4)
                *reinterpret_cast<float4*>(&b[j]) =
                    *reinterpret_cast<const float4*>(&Bs[k][tcol + j]);
            #pragma unroll
            for (int i = 0; i < TM; ++i)
                #pragma unroll
                for (int j = 0; j < TN; ++j)
                    acc[i][j] = fmaf(a[i], b[j], acc[i][j]);
        }
        __syncthreads();
    }

    // ---- epilogue ----
    float bvals[TN];
    if (BIAS) {
        #pragma unroll
        for (int j = 0; j < TN; ++j) bvals[j] = bias[bn + tcol + j];
    }
    #pragma unroll
    for (int i = 0; i < TM; ++i) {
        float* crow = C + (long long)(bm + trow + i) * N + bn + tcol;
        #pragma unroll
        for (int j0 = 0; j0 < TN; j0 += 4) {
            float4 o;
            o.x = acc[i][j0 + 0] + (BIAS ? bvals[j0 + 0] : 0.f);
            o.y = acc[i][j0 + 1] + (BIAS ? bvals[j0 + 1] : 0.f);
            o.z = acc[i][j0 + 2] + (BIAS ? bvals[j0 + 2] : 0.f);
            o.w = acc[i][j0 + 3] + (BIAS ? bvals[j0 + 3] : 0.f);
            *reinterpret_cast<float4*>(crow + j0) = o;
        }
    }
}

// ---------------------------------------------------------------------------
// Row softmax over SEQ=2048 columns. One 256-thread block per row.
// ---------------------------------------------------------------------------
__global__ __launch_bounds__(256)
void softmax_kernel(float* __restrict__ Sm)
{
    const int n = SEQ;
    float* row = Sm + (size_t)blockIdx.x * n;
    const int tid = threadIdx.x;

    float v[8];
    float m = -3.4e38f;
    #pragma unroll
    for (int i = 0; i < 8; ++i) {
        v[i] = row[tid + 256 * i];
        m = fmaxf(m, v[i]);
    }

    __shared__ float red[8];
    #pragma unroll
    for (int o = 16; o > 0; o >>= 1) m = fmaxf(m, __shfl_xor_sync(0xffffffffu, m, o));
    if ((tid & 31) == 0) red[tid >> 5] = m;
    __syncthreads();
    float bm = red[0];
    #pragma unroll
    for (int w = 1; w < 8; ++w) bm = fmaxf(bm, red[w]);
    __syncthreads();

    float s = 0.f;
    #pragma unroll
    for (int i = 0; i < 8; ++i) {
        v[i] = __expf(v[i] - bm);
        s += v[i];
    }
    #pragma unroll
    for (int o = 16; o > 0; o >>= 1) s += __shfl_xor_sync(0xffffffffu, s, o);
    if ((tid & 31) == 0) red[tid >> 5] = s;
    __syncthreads();
    float bs = 0.f;
    #pragma unroll
    for (int w = 0; w < 8; ++w) bs += red[w];

    const float inv = 1.0f / bs;
    #pragma unroll
    for (int i = 0; i < 8; ++i) row[tid + 256 * i] = v[i] * inv;
}

// ---------------------------------------------------------------------------
// Launch
// ---------------------------------------------------------------------------
extern "C" void kernel_launch(void* const* d_in, const int* in_sizes, int n_in,
                              void* d_out, int out_size)
{
    const float* query = (const float*)d_in[0];
    const float* kv    = (const float*)d_in[1];
    const float* Wq    = (const float*)d_in[2];
    const float* bq    = (const float*)d_in[3];
    const float* Wk    = (const float*)d_in[4];
    const float* bk    = (const float*)d_in[5];
    const float* Wv    = (const float*)d_in[6];
    const float* bv    = (const float*)d_in[7];
    const float* Wo    = (const float*)d_in[8];
    const float* bo    = (const float*)d_in[9];
    float* out = (float*)d_out;

    float *Q, *K, *V, *S, *C;
    cudaGetSymbolAddress((void**)&Q, g_Q);
    cudaGetSymbolAddress((void**)&K, g_K);
    cudaGetSymbolAddress((void**)&V, g_V);
    cudaGetSymbolAddress((void**)&S, g_S);
    cudaGetSymbolAddress((void**)&C, g_C);

    const int M  = BATCH * SEQ;             // 8192
    const long long sQKV = (long long)SEQ * DIM;   // per-batch Q/K/V stride
    const long long sS   = (long long)SEQ * SEQ;   // per-batch score stride

    // Projections: [8192,1024] x [1024,1024] + bias
    {
        dim3 grid(DIM / BN, M / BM, 1);
        sgemm_kernel<false, true><<<grid, NTHREADS>>>(query, Wq, bq, Q, M, DIM, DIM, 0, 0, 0);
        sgemm_kernel<false, true><<<grid, NTHREADS>>>(kv,    Wk, bk, K, M, DIM, DIM, 0, 0, 0);
        sgemm_kernel<false, true><<<grid, NTHREADS>>>(kv,    Wv, bv, V, M, DIM, DIM, 0, 0, 0);
    }

    // Scores: per batch, [2048,1024] x [2048,1024]^T -> [2048,2048]
    {
        dim3 grid(SEQ / BN, SEQ / BM, BATCH);
        sgemm_kernel<true, false><<<grid, NTHREADS>>>(Q, K, nullptr, S,
                                                      SEQ, SEQ, DIM, sQKV, sQKV, sS);
    }

    // Softmax over rows
    softmax_kernel<<<BATCH * SEQ, 256>>>(S);

    // Context: per batch, [2048,2048] x [2048,1024] -> [2048,1024]
    {
        dim3 grid(DIM / BN, SEQ / BM, BATCH);
        sgemm_kernel<false, false><<<grid, NTHREADS>>>(S, V, nullptr, C,
                                                       SEQ, DIM, SEQ, sS, sQKV, sQKV);
    }

    // Output projection: [8192,1024] x [1024,1024] + bias -> d_out
    {
        dim3 grid(DIM / BN, M / BM, 1);
        sgemm_kernel<false, true><<<grid, NTHREADS>>>(C, Wo, bo, out, M, DIM, DIM, 0, 0, 0);
    }
}

// round 13
// speedup vs baseline: 2.9214x; 2.9191x over previous
#include <cuda_runtime.h>
#include <cuda_bf16.h>
#include <cstdint>

#define BATCH 4
#define SEQ   2048
#define DIM   1024
#define MTOT  (BATCH*SEQ)
#define DD    ((size_t)DIM*DIM)
#define SMEM_DYN 132096   // 2 x 64KB stages + align pad; also covers 66KB epilogue

// ---------------- device scratch (allocation-free rule) --------------------
__device__ __align__(16) __nv_bfloat16 g_Xq_hi [(size_t)MTOT*DIM], g_Xq_lo [(size_t)MTOT*DIM];
__device__ __align__(16) __nv_bfloat16 g_Xkv_hi[(size_t)MTOT*DIM], g_Xkv_lo[(size_t)MTOT*DIM];
__device__ __align__(16) __nv_bfloat16 g_Wt_hi [4*DD],             g_Wt_lo [4*DD];
__device__ __align__(16) __nv_bfloat16 g_Q_hi  [(size_t)MTOT*DIM], g_Q_lo  [(size_t)MTOT*DIM];
__device__ __align__(16) __nv_bfloat16 g_K_hi  [(size_t)MTOT*DIM], g_K_lo  [(size_t)MTOT*DIM];
__device__ __align__(16) __nv_bfloat16 g_Vt_hi [(size_t)BATCH*DIM*SEQ], g_Vt_lo[(size_t)BATCH*DIM*SEQ];
__device__ __align__(16) float         g_S     [(size_t)BATCH*SEQ*SEQ];
__device__ __align__(16) __nv_bfloat16 g_P_hi  [(size_t)BATCH*SEQ*SEQ], g_P_lo[(size_t)BATCH*SEQ*SEQ];
__device__ __align__(16) __nv_bfloat16 g_C_hi  [(size_t)MTOT*DIM], g_C_lo  [(size_t)MTOT*DIM];

// ---------------- helpers ---------------------------------------------------
#define SWZ(o) ((o) ^ (((o) >> 3) & 0x70))

static __device__ __forceinline__ uint32_t smem_u32(const void* p) {
    uint32_t a;
    asm("{ .reg .u64 t; cvta.to.shared.u64 t, %1; cvt.u32.u64 %0, t; }" : "=r"(a) : "l"(p));
    return a;
}
static __device__ __forceinline__ void ldmx4(uint32_t* r, uint32_t addr) {
    asm volatile("ldmatrix.sync.aligned.m8n8.x4.shared.b16 {%0,%1,%2,%3}, [%4];"
                 : "=r"(r[0]), "=r"(r[1]), "=r"(r[2]), "=r"(r[3]) : "r"(addr));
}
static __device__ __forceinline__ void mma16816(float* c, const uint32_t* a,
                                                uint32_t b0, uint32_t b1) {
    asm volatile("mma.sync.aligned.m16n8k16.row.col.f32.bf16.bf16.f32 "
                 "{%0,%1,%2,%3}, {%4,%5,%6,%7}, {%8,%9}, {%0,%1,%2,%3};"
                 : "+f"(c[0]), "+f"(c[1]), "+f"(c[2]), "+f"(c[3])
                 : "r"(a[0]), "r"(a[1]), "r"(a[2]), "r"(a[3]), "r"(b0), "r"(b1));
}
static __device__ __forceinline__ void cpa16(uint32_t dst, const void* src) {
    asm volatile("cp.async.cg.shared.global [%0], [%1], 16;" :: "r"(dst), "l"(src) : "memory");
}
static __device__ __forceinline__ void split2(float v0, float v1, uint32_t& hp, uint32_t& lp) {
    __nv_bfloat16 h0 = __float2bfloat16_rn(v0), h1 = __float2bfloat16_rn(v1);
    __nv_bfloat16 l0 = __float2bfloat16_rn(v0 - __bfloat162float(h0));
    __nv_bfloat16 l1 = __float2bfloat16_rn(v1 - __bfloat162float(h1));
    hp = (uint32_t)__bfloat16_as_ushort(h0) | ((uint32_t)__bfloat16_as_ushort(h1) << 16);
    lp = (uint32_t)__bfloat16_as_ushort(l0) | ((uint32_t)__bfloat16_as_ushort(l1) << 16);
}

// stage fill: 4 tiles of [128 rows x 64 bf16] (128B rows, SW128), cp.async 16B
static __device__ __forceinline__ void fill_stage(uint32_t db,
        const __nv_bfloat16* Ah, const __nv_bfloat16* Al,
        const __nv_bfloat16* Bh, const __nv_bfloat16* Bl, int K, int tid)
{
    const __nv_bfloat16* srcs[4] = { Ah, Al, Bh, Bl };
    #pragma unroll
    for (int op = 0; op < 4; ++op) {
        const __nv_bfloat16* sp = srcs[op];
        #pragma unroll
        for (int t = 0; t < 4; ++t) {
            int id = tid + t * 256, row = id >> 3, c = id & 7;
            uint32_t o = row * 128 + c * 16;
            cpa16(db + op * 16384 + SWZ(o), sp + (size_t)row * K + c * 8);
        }
    }
}

// ===========================================================================
// split-bf16 GEMM on HMMA (mma.sync): C[128,128]/CTA = sum_k A[m,k]*B[n,k]
// A,B K-major bf16 hi/lo.  MODE: 0 fp32 out, 1 bf16 hi/lo out, 2 transposed.
// ===========================================================================
template <int MODE, bool BIAS>
__global__ __launch_bounds__(256, 1)
void gemm_tc(const __nv_bfloat16* __restrict__ Ahi, const __nv_bfloat16* __restrict__ Alo,
             const __nv_bfloat16* __restrict__ Bhi, const __nv_bfloat16* __restrict__ Blo,
             const float* __restrict__ bias, float* __restrict__ Cf,
             __nv_bfloat16* __restrict__ Chi, __nv_bfloat16* __restrict__ Clo,
             int K, long long sA, long long sB, long long sC, int ldC, int trows)
{
    extern __shared__ char dsm[];
    const int tid = threadIdx.x, lane = tid & 31, wid = tid >> 5;
    const int wm = wid & 3, wn = wid >> 2;                 // warp tile: rows wm*32, cols wn*64
    const int bm = blockIdx.y * 128, bn = blockIdx.x * 128, z = blockIdx.z;

    const uint32_t raw   = smem_u32(dsm);
    const uint32_t abase = (raw + 1023u) & ~1023u;
    char* sm = dsm + (abase - raw);

    const __nv_bfloat16* srcAh = Ahi + (size_t)z * sA + (size_t)bm * K;
    const __nv_bfloat16* srcAl = Alo + (size_t)z * sA + (size_t)bm * K;
    const __nv_bfloat16* srcBh = Bhi + (size_t)z * sB + (size_t)bn * K;
    const __nv_bfloat16* srcBl = Blo + (size_t)z * sB + (size_t)bn * K;

    // per-lane ldmatrix address components
    const int arow = wm * 32 + (lane & 15);     // + mf*16
    const int akc  = lane >> 4;                 // k-chunk (0/1)
    const int brow = wn * 64 + ((lane >> 4) << 3) + (lane & 7);  // + nfp*16
    const int bkc  = (lane >> 3) & 1;

    float acc[2][8][4];
    #pragma unroll
    for (int i = 0; i < 2; ++i)
        #pragma unroll
        for (int j = 0; j < 8; ++j)
            #pragma unroll
            for (int q = 0; q < 4; ++q) acc[i][j][q] = 0.f;

    const int nst = K >> 6;

    fill_stage(abase, srcAh, srcAl, srcBh, srcBl, K, tid);
    asm volatile("cp.async.commit_group;" ::: "memory");

    for (int s = 0; s < nst; ++s) {
        if (s + 1 < nst) {
            fill_stage(abase + ((s + 1) & 1) * 65536,
                       srcAh + (s + 1) * 64, srcAl + (s + 1) * 64,
                       srcBh + (s + 1) * 64, srcBl + (s + 1) * 64, K, tid);
            asm volatile("cp.async.commit_group;" ::: "memory");
            asm volatile("cp.async.wait_group 1;" ::: "memory");
        } else {
            asm volatile("cp.async.wait_group 0;" ::: "memory");
        }
        __syncthreads();

        const uint32_t bufb = abase + (s & 1) * 65536;
        #pragma unroll
        for (int k16 = 0; k16 < 4; ++k16) {
            uint32_t ah[2][4], al[2][4];
            #pragma unroll
            for (int mf = 0; mf < 2; ++mf) {
                int row = arow + mf * 16;
                uint32_t off = row * 128 + (((k16 * 2 + akc) * 16) ^ ((row & 7) << 4));
                ldmx4(ah[mf], bufb + off);
                ldmx4(al[mf], bufb + 16384 + off);
            }
            #pragma unroll
            for (int nfp = 0; nfp < 4; ++nfp) {
                int row = brow + nfp * 16;
                uint32_t off = row * 128 + (((k16 * 2 + bkc) * 16) ^ ((row & 7) << 4));
                uint32_t bh[4], bl[4];
                ldmx4(bh, bufb + 32768 + off);
                ldmx4(bl, bufb + 49152 + off);
                #pragma unroll
                for (int mf = 0; mf < 2; ++mf) {
                    mma16816(acc[mf][2*nfp],   ah[mf], bh[0], bh[1]);   // hi*hi
                    mma16816(acc[mf][2*nfp+1], ah[mf], bh[2], bh[3]);
                    mma16816(acc[mf][2*nfp],   ah[mf], bl[0], bl[1]);   // hi*lo
                    mma16816(acc[mf][2*nfp+1], ah[mf], bl[2], bl[3]);
                    mma16816(acc[mf][2*nfp],   al[mf], bh[0], bh[1]);   // lo*hi
                    mma16816(acc[mf][2*nfp+1], al[mf], bh[2], bh[3]);
                }
            }
        }
        __syncthreads();
    }

    // ---- epilogue: frags -> smem staging [128][129] fp32 ----
    float* os = reinterpret_cast<float*>(sm);
    #pragma unroll
    for (int mf = 0; mf < 2; ++mf)
        #pragma unroll
        for (int nf = 0; nf < 8; ++nf) {
            int r0  = wm * 32 + mf * 16 + (lane >> 2);
            int col = wn * 64 + nf * 8 + 2 * (lane & 3);
            os[r0 * 129 + col]           = acc[mf][nf][0];
            os[r0 * 129 + col + 1]       = acc[mf][nf][1];
            os[(r0 + 8) * 129 + col]     = acc[mf][nf][2];
            os[(r0 + 8) * 129 + col + 1] = acc[mf][nf][3];
        }
    __syncthreads();

    if (MODE == 0) {
        float* outp = Cf + (size_t)z * sC;
        for (int idx = tid; idx < 8192; idx += 256) {
            int r = idx >> 6, c2 = (idx & 63) * 2;
            float2 v = { os[r * 129 + c2], os[r * 129 + c2 + 1] };
            if (BIAS) { v.x += bias[bn + c2]; v.y += bias[bn + c2 + 1]; }
            *reinterpret_cast<float2*>(outp + (size_t)(bm + r) * ldC + bn + c2) = v;
        }
    } else if (MODE == 1) {
        for (int idx = tid; idx < 8192; idx += 256) {
            int r = idx >> 6, c2 = (idx & 63) * 2;
            float v0 = os[r * 129 + c2], v1 = os[r * 129 + c2 + 1];
            if (BIAS) { v0 += bias[bn + c2]; v1 += bias[bn + c2 + 1]; }
            uint32_t hp, lp;
            split2(v0, v1, hp, lp);
            size_t o = (size_t)z * sC + (size_t)(bm + r) * ldC + bn + c2;
            *reinterpret_cast<uint32_t*>(Chi + o) = hp;
            *reinterpret_cast<uint32_t*>(Clo + o) = lp;
        }
    } else {  // transposed: out[batch][e=bn+n][t=mbase+m], bias over e
        const int batch = bm / trows, mbase = bm - batch * trows;
        for (int idx = tid; idx < 8192; idx += 256) {
            int n = idx >> 6, m2 = (idx & 63) * 2;
            float bb = BIAS ? bias[bn + n] : 0.f;
            uint32_t hp, lp;
            split2(os[m2 * 129 + n] + bb, os[(m2 + 1) * 129 + n] + bb, hp, lp);
            size_t o = (size_t)batch * sC + (size_t)(bn + n) * trows + mbase + m2;
            *reinterpret_cast<uint32_t*>(Chi + o) = hp;
            *reinterpret_cast<uint32_t*>(Clo + o) = lp;
        }
    }
}

// ---------------- prep kernels ---------------------------------------------
__global__ __launch_bounds__(256)
void split_rm(const float4* __restrict__ X, uint32_t* __restrict__ H,
              uint32_t* __restrict__ L, int n4)
{
    int i = blockIdx.x * 256 + threadIdx.x;
    if (i >= n4) return;
    float4 v = X[i];
    uint32_t h0, l0, h1, l1;
    split2(v.x, v.y, h0, l0);
    split2(v.z, v.w, h1, l1);
    H[2*i] = h0; H[2*i+1] = h1; L[2*i] = l0; L[2*i+1] = l1;
}

// W[k][n] fp32 -> Wt[n][k] bf16 hi/lo
__global__ __launch_bounds__(256)
void split_tr(const float* __restrict__ W, __nv_bfloat16* __restrict__ TH,
              __nv_bfloat16* __restrict__ TL)
{
    __shared__ float t[32][33];
    const int n0 = blockIdx.x * 32, k0 = blockIdx.y * 32;
    const int tx = threadIdx.x, ty = threadIdx.y;
    #pragma unroll
    for (int j = 0; j < 4; ++j)
        t[ty + 8*j][tx] = W[(size_t)(k0 + ty + 8*j) * DIM + n0 + tx];
    __syncthreads();
    #pragma unroll
    for (int j = 0; j < 4; ++j) {
        const int r = ty + 8*j;
        const float v = t[tx][r];
        __nv_bfloat16 h = __float2bfloat16_rn(v);
        __nv_bfloat16 l = __float2bfloat16_rn(v - __bfloat162float(h));
        const size_t o = (size_t)(n0 + r) * DIM + k0 + tx;
        TH[o] = h; TL[o] = l;
    }
}

// row softmax over SEQ cols; writes P split to bf16 hi/lo
__global__ __launch_bounds__(256)
void softmax_split(const float* __restrict__ S, uint32_t* __restrict__ Ph,
                   uint32_t* __restrict__ Pl)
{
    const size_t rb = (size_t)blockIdx.x * SEQ;
    const int tid = threadIdx.x;
    float v[8];
    *reinterpret_cast<float4*>(v)     = *reinterpret_cast<const float4*>(S + rb + tid * 8);
    *reinterpret_cast<float4*>(v + 4) = *reinterpret_cast<const float4*>(S + rb + tid * 8 + 4);

    float m = v[0];
    #pragma unroll
    for (int i = 1; i < 8; ++i) m = fmaxf(m, v[i]);
    __shared__ float red[8];
    #pragma unroll
    for (int o = 16; o > 0; o >>= 1) m = fmaxf(m, __shfl_xor_sync(0xffffffffu, m, o));
    if ((tid & 31) == 0) red[tid >> 5] = m;
    __syncthreads();
    float bm = red[0];
    #pragma unroll
    for (int w = 1; w < 8; ++w) bm = fmaxf(bm, red[w]);
    __syncthreads();

    float s = 0.f;
    #pragma unroll
    for (int i = 0; i < 8; ++i) { v[i] = __expf(v[i] - bm); s += v[i]; }
    #pragma unroll
    for (int o = 16; o > 0; o >>= 1) s += __shfl_xor_sync(0xffffffffu, s, o);
    if ((tid & 31) == 0) red[tid >> 5] = s;
    __syncthreads();
    float bs = 0.f;
    #pragma unroll
    for (int w = 0; w < 8; ++w) bs += red[w];
    const float inv = 1.0f / bs;

    const size_t ob = (rb + tid * 8) >> 1;
    #pragma unroll
    for (int i = 0; i < 4; ++i) {
        uint32_t hp, lp;
        split2(v[2*i] * inv, v[2*i+1] * inv, hp, lp);
        Ph[ob + i] = hp; Pl[ob + i] = lp;
    }
}

// ---------------- launch ----------------------------------------------------
extern "C" void kernel_launch(void* const* d_in, const int* in_sizes, int n_in,
                              void* d_out, int out_size)
{
    const float* query = (const float*)d_in[0];
    const float* kv    = (const float*)d_in[1];
    const float* Wq    = (const float*)d_in[2];
    const float* bq    = (const float*)d_in[3];
    const float* Wk    = (const float*)d_in[4];
    const float* bk    = (const float*)d_in[5];
    const float* Wv    = (const float*)d_in[6];
    const float* bv    = (const float*)d_in[7];
    const float* Wo    = (const float*)d_in[8];
    const float* bo    = (const float*)d_in[9];
    float* out = (float*)d_out;

    static bool attr_done = false;
    if (!attr_done) {
        cudaFuncSetAttribute(gemm_tc<0, false>, cudaFuncAttributeMaxDynamicSharedMemorySize, SMEM_DYN);
        cudaFuncSetAttribute(gemm_tc<0, true>,  cudaFuncAttributeMaxDynamicSharedMemorySize, SMEM_DYN);
        cudaFuncSetAttribute(gemm_tc<1, true>,  cudaFuncAttributeMaxDynamicSharedMemorySize, SMEM_DYN);
        cudaFuncSetAttribute(gemm_tc<1, false>, cudaFuncAttributeMaxDynamicSharedMemorySize, SMEM_DYN);
        cudaFuncSetAttribute(gemm_tc<2, true>,  cudaFuncAttributeMaxDynamicSharedMemorySize, SMEM_DYN);
        attr_done = true;
    }

    __nv_bfloat16 *Xqh, *Xql, *Xkh, *Xkl, *Wth, *Wtl, *Qh, *Ql, *Kh, *Kl, *Vth, *Vtl, *Pph, *Ppl, *Ch, *Cl;
    float* S;
    cudaGetSymbolAddress((void**)&Xqh, g_Xq_hi);  cudaGetSymbolAddress((void**)&Xql, g_Xq_lo);
    cudaGetSymbolAddress((void**)&Xkh, g_Xkv_hi); cudaGetSymbolAddress((void**)&Xkl, g_Xkv_lo);
    cudaGetSymbolAddress((void**)&Wth, g_Wt_hi);  cudaGetSymbolAddress((void**)&Wtl, g_Wt_lo);
    cudaGetSymbolAddress((void**)&Qh,  g_Q_hi);   cudaGetSymbolAddress((void**)&Ql,  g_Q_lo);
    cudaGetSymbolAddress((void**)&Kh,  g_K_hi);   cudaGetSymbolAddress((void**)&Kl,  g_K_lo);
    cudaGetSymbolAddress((void**)&Vth, g_Vt_hi);  cudaGetSymbolAddress((void**)&Vtl, g_Vt_lo);
    cudaGetSymbolAddress((void**)&S,   g_S);
    cudaGetSymbolAddress((void**)&Pph, g_P_hi);   cudaGetSymbolAddress((void**)&Ppl, g_P_lo);
    cudaGetSymbolAddress((void**)&Ch,  g_C_hi);   cudaGetSymbolAddress((void**)&Cl,  g_C_lo);

    const long long sQKV = (long long)SEQ * DIM;
    const long long sS   = (long long)SEQ * SEQ;
    const long long sVt  = (long long)DIM * SEQ;

    // --- prep: split inputs, transpose+split weights ---
    {
        int n4 = MTOT * DIM / 4;
        split_rm<<<n4 / 256, 256>>>((const float4*)query, (uint32_t*)Xqh, (uint32_t*)Xql, n4);
        split_rm<<<n4 / 256, 256>>>((const float4*)kv,    (uint32_t*)Xkh, (uint32_t*)Xkl, n4);
        dim3 g(DIM / 32, DIM / 32), blk(32, 8);
        split_tr<<<g, blk>>>(Wq, Wth + 0*DD, Wtl + 0*DD);
        split_tr<<<g, blk>>>(Wk, Wth + 1*DD, Wtl + 1*DD);
        split_tr<<<g, blk>>>(Wv, Wth + 2*DD, Wtl + 2*DD);
        split_tr<<<g, blk>>>(Wo, Wth + 3*DD, Wtl + 3*DD);
    }

    // --- projections: [8192,1024] x W -> Q/K (bf16 hi/lo), V (transposed) ---
    {
        dim3 grid(DIM / 128, MTOT / 128, 1);
        gemm_tc<1, true><<<grid, 256, SMEM_DYN>>>(Xqh, Xql, Wth + 0*DD, Wtl + 0*DD, bq,
                                                  nullptr, Qh, Ql, DIM, 0, 0, 0, DIM, 0);
        gemm_tc<1, true><<<grid, 256, SMEM_DYN>>>(Xkh, Xkl, Wth + 1*DD, Wtl + 1*DD, bk,
                                                  nullptr, Kh, Kl, DIM, 0, 0, 0, DIM, 0);
        gemm_tc<2, true><<<grid, 256, SMEM_DYN>>>(Xkh, Xkl, Wth + 2*DD, Wtl + 2*DD, bv,
                                                  nullptr, Vth, Vtl, DIM, 0, 0, sVt, 0, SEQ);
    }
    // --- scores: per batch Q K^T -> S fp32 ---
    {
        dim3 grid(SEQ / 128, SEQ / 128, BATCH);
        gemm_tc<0, false><<<grid, 256, SMEM_DYN>>>(Qh, Ql, Kh, Kl, nullptr,
                                                   S, nullptr, nullptr, DIM, sQKV, sQKV, sS, SEQ, 0);
    }
    // --- softmax + split ---
    softmax_split<<<BATCH * SEQ, 256>>>(S, (uint32_t*)Pph, (uint32_t*)Ppl);

    // --- context: P @ Vt -> C bf16 hi/lo ---
    {
        dim3 grid(DIM / 128, SEQ / 128, BATCH);
        gemm_tc<1, false><<<grid, 256, SMEM_DYN>>>(Pph, Ppl, Vth, Vtl, nullptr,
                                                   nullptr, Ch, Cl, SEQ, sS, sVt, sQKV, DIM, 0);
    }
    // --- output projection -> d_out fp32 ---
    {
        dim3 grid(DIM / 128, MTOT / 128, 1);
        gemm_tc<0, true><<<grid, 256, SMEM_DYN>>>(Ch, Cl, Wth + 3*DD, Wtl + 3*DD, bo,
                                                  out, nullptr, nullptr, DIM, 0, 0, 0, DIM, 0);
    }
}